// round 5
// baseline (speedup 1.0000x reference)
#include <cuda_runtime.h>
#include <math.h>

#define N_NODES 20000
#define N_EDGES 320000
#define D 128
#define ETOT (N_EDGES + N_NODES)   // edges + self-loops = 340000
#define NG 64

// ---------------- scratch (device globals; no allocation allowed) ----------------
__device__ float g_bufA[N_NODES * D];
__device__ float g_bufB[N_NODES * D];
__device__ float g_hg[N_NODES * D];     // h @ gat_W
__device__ float g_hc[N_NODES * D];     // h @ gcn_W
__device__ float g_es[N_NODES];         // hg . a_src
__device__ float g_ed[N_NODES];         // hg . a_dst
__device__ float g_s[N_NODES];          // segment sum of exp
__device__ float g_dinv[N_NODES];       // deg^-1/2 (also used as deg accumulator)
__device__ float g_ebuf[ETOT];          // per-edge exp(e)
__device__ float g_pooled[NG * D];
__device__ float g_cnt[NG];

// ---------------- helpers ----------------
__device__ __forceinline__ unsigned f2tf32(float a) {
    unsigned r;
    asm("cvt.rna.tf32.f32 %0, %1;" : "=r"(r) : "f"(a));
    return r;
}

__device__ __forceinline__ void mma_tf32(float* c, unsigned a0, unsigned a1, unsigned a2,
                                         unsigned a3, unsigned b0, unsigned b1) {
    asm volatile(
        "mma.sync.aligned.m16n8k8.row.col.f32.tf32.tf32.f32 "
        "{%0,%1,%2,%3}, {%4,%5,%6,%7}, {%8,%9}, {%0,%1,%2,%3};"
        : "+f"(c[0]), "+f"(c[1]), "+f"(c[2]), "+f"(c[3])
        : "r"(a0), "r"(a1), "r"(a2), "r"(a3), "r"(b0), "r"(b1));
}

// ---------------- setup kernels ----------------
__global__ void zero_kernel() {
    int i = blockIdx.x * blockDim.x + threadIdx.x;
    if (i < N_NODES) g_dinv[i] = 0.0f;
    if (i < NG * D)  g_pooled[i] = 0.0f;
    if (i < NG)      g_cnt[i] = 0.0f;
}

__global__ void deg_kernel(const int* __restrict__ dst) {
    int i = blockIdx.x * blockDim.x + threadIdx.x;
    if (i >= ETOT) return;
    int d = (i < N_EDGES) ? dst[i] : (i - N_EDGES);
    atomicAdd(&g_dinv[d], 1.0f);
}

__global__ void deg_fin_kernel(const int* __restrict__ batch) {
    int i = blockIdx.x * blockDim.x + threadIdx.x;
    if (i >= N_NODES) return;
    g_dinv[i] = rsqrtf(fmaxf(g_dinv[i], 1.0f));
    atomicAdd(&g_cnt[batch[i]], 1.0f);
}

// ---------------- GEMM v4: tensor-core 3xTF32, fragment-major B ----------------
// 128 rows x 128 cols per block, 8 warps (16 rows each), K=128.
// B (= W split hi/lo) is stored in smem in MMA-fragment order:
//   Bfrag[(nt*16 + kt)*32 + tig*8 + gid] : float4 = (hi[k0+tig], lo[k0+tig],
//                                                    hi[k0+tig+4], lo[k0+tig+4])
// -> one conflict-free LDS.128 per (kt, nt) per thread.
#define WP 132   // A-tile pitch (floats); (gid*132+tig) mod 32 distinct -> conflict-free
#define BFRAG_BYTES (16 * 16 * 32 * 16)           // 131072
#define SMEM_TOTAL_G (BFRAG_BYTES + 128 * WP * 4 + 3 * 128 * 4)

__global__ void __launch_bounds__(256, 1)
gemm4(const float* __restrict__ x, int insel, int relu,
      const float* __restrict__ gatW, const float* __restrict__ gcnW,
      const float* __restrict__ linW,
      const float* __restrict__ gat_b, const float* __restrict__ gcn_b,
      const float* __restrict__ lin_b,
      const float* __restrict__ a0v, const float* __restrict__ a1v,
      int outsel) {
    extern __shared__ char smraw[];
    float*  Bf    = (float*)smraw;                        // fragment-major W split
    const float4* Bf4 = (const float4*)smraw;
    float*  As    = (float*)(smraw + BFRAG_BYTES);        // 128 x WP fp32
    float*  biasS = As + 128 * WP;                        // 128
    float*  a0S   = biasS + 128;                          // 128
    float*  a1S   = a0S + 128;                            // 128

    const float* hin = (insel == 0) ? x : ((insel == 1) ? g_bufA : g_bufB);
    int mat = blockIdx.y;
    const float* W = (mat == 0) ? gatW : ((mat == 1) ? gcnW : linW);
    float* out = (mat == 0) ? g_hg : ((mat == 1) ? g_hc : (outsel ? g_bufB : g_bufA));

    int row0 = blockIdx.x * 128;
    int tid = threadIdx.x;

    // ---- load A tile (128 x 128 fp32, relu opt, zero-fill OOB) ----
    for (int i = tid; i < 128 * D / 4; i += 256) {
        int r = (i * 4) / D;
        int c = (i * 4) % D;
        float4 v = make_float4(0.f, 0.f, 0.f, 0.f);
        if (row0 + r < N_NODES) v = *(const float4*)&hin[(size_t)(row0 + r) * D + c];
        if (relu) {
            v.x = fmaxf(v.x, 0.f); v.y = fmaxf(v.y, 0.f);
            v.z = fmaxf(v.z, 0.f); v.w = fmaxf(v.w, 0.f);
        }
        *(float4*)&As[r * WP + c] = v;
    }
    // ---- load W, split into tf32 hi/lo, scatter into fragment-major layout ----
    // source element (k, n) -> fragment (nt = n/8, kt = k/8), lane slot
    // tig = k%4, half = (k%8)/4, gid = n%8; payload float4 slot components:
    //   [half*2] = hi, [half*2+1] = lo.
    for (int i = tid; i < D * D / 4; i += 256) {
        int k = (i * 4) / D;
        int n = (i * 4) % D;
        float4 v = *(const float4*)&W[k * D + n];
        int kt = k >> 3, r = k & 7;
        int tig = r & 3, half = r >> 2;
        int nt = n >> 3, gbase = n & 7;   // gbase in {0,4}
        float w4[4] = {v.x, v.y, v.z, v.w};
#pragma unroll
        for (int j = 0; j < 4; j++) {
            unsigned hi = f2tf32(w4[j]);
            float res = w4[j] - __uint_as_float(hi);
            unsigned lo = f2tf32(res);
            int idx = (((nt * 16 + kt) * 32) + tig * 8 + gbase + j) * 4 + half * 2;
            Bf[idx]     = __uint_as_float(hi);
            Bf[idx + 1] = __uint_as_float(lo);
        }
    }
    // ---- aux vectors ----
    if (tid < 128) {
        biasS[tid] = (mat == 2) ? (lin_b[tid] + gat_b[tid] + gcn_b[tid]) : 0.f;
        if (mat == 0) { a0S[tid] = a0v[tid]; a1S[tid] = a1v[tid]; }
    }
    __syncthreads();

    int warp = tid >> 5;
    int lane = tid & 31;
    int gid = lane >> 2;   // groupID 0..7
    int tig = lane & 3;    // thread-in-group 0..3
    int mrow0 = warp * 16;
    int lofs = tig * 8 + gid;   // fragment-internal lane offset

    float acc[16][4];
#pragma unroll
    for (int nt = 0; nt < 16; nt++)
#pragma unroll
        for (int j = 0; j < 4; j++) acc[nt][j] = 0.f;

#pragma unroll 2
    for (int kt = 0; kt < 16; kt++) {
        int k0 = kt * 8;
        // A fragment (m16k8): rows mrow0+gid, +8; cols k0+tig, +4 (conflict-free)
        float av[4];
        av[0] = As[(mrow0 + gid) * WP + k0 + tig];
        av[1] = As[(mrow0 + gid + 8) * WP + k0 + tig];
        av[2] = As[(mrow0 + gid) * WP + k0 + tig + 4];
        av[3] = As[(mrow0 + gid + 8) * WP + k0 + tig + 4];
        unsigned ah[4], al[4];
#pragma unroll
        for (int j = 0; j < 4; j++) {
            ah[j] = f2tf32(av[j]);
            al[j] = f2tf32(av[j] - __uint_as_float(ah[j]));
        }
#pragma unroll
        for (int nt = 0; nt < 16; nt++) {
            float4 b = Bf4[(nt * 16 + kt) * 32 + lofs];   // one LDS.128, conflict-free
            unsigned bh0 = __float_as_uint(b.x), bl0 = __float_as_uint(b.y);
            unsigned bh1 = __float_as_uint(b.z), bl1 = __float_as_uint(b.w);
            mma_tf32(acc[nt], ah[0], ah[1], ah[2], ah[3], bh0, bh1);
            mma_tf32(acc[nt], ah[0], ah[1], ah[2], ah[3], bl0, bl1);
            mma_tf32(acc[nt], al[0], al[1], al[2], al[3], bh0, bh1);
        }
    }

    // ---- epilogue: bias + store. C layout: c0,c1 -> (row gid, cols 2tig,2tig+1);
    //      c2,c3 -> (row gid+8, same cols). ----
    int rA = row0 + mrow0 + gid;
    int rB = rA + 8;
#pragma unroll
    for (int nt = 0; nt < 16; nt++) {
        int col = nt * 8 + tig * 2;
        float b0 = biasS[col], b1 = biasS[col + 1];
        if (rA < N_NODES)
            *(float2*)&out[(size_t)rA * D + col] = make_float2(acc[nt][0] + b0, acc[nt][1] + b1);
        if (rB < N_NODES)
            *(float2*)&out[(size_t)rB * D + col] = make_float2(acc[nt][2] + b0, acc[nt][3] + b1);
    }

    // ---- fused node_prep for GAT matrix ----
    if (mat == 0) {
        float esA = 0.f, edA = 0.f, esB = 0.f, edB = 0.f;
#pragma unroll
        for (int nt = 0; nt < 16; nt++) {
            int col = nt * 8 + tig * 2;
            float p0 = a0S[col], p1 = a0S[col + 1];
            float q0 = a1S[col], q1 = a1S[col + 1];
            esA += acc[nt][0] * p0 + acc[nt][1] * p1;
            edA += acc[nt][0] * q0 + acc[nt][1] * q1;
            esB += acc[nt][2] * p0 + acc[nt][3] * p1;
            edB += acc[nt][2] * q0 + acc[nt][3] * q1;
        }
#pragma unroll
        for (int o = 1; o < 4; o <<= 1) {
            esA += __shfl_xor_sync(0xFFFFFFFFu, esA, o);
            edA += __shfl_xor_sync(0xFFFFFFFFu, edA, o);
            esB += __shfl_xor_sync(0xFFFFFFFFu, esB, o);
            edB += __shfl_xor_sync(0xFFFFFFFFu, edB, o);
        }
        if (tig == 0) {
            if (rA < N_NODES) { g_es[rA] = esA; g_ed[rA] = edA; g_s[rA] = 0.f; }
            if (rB < N_NODES) { g_es[rB] = esB; g_ed[rB] = edB; g_s[rB] = 0.f; }
        }
    }
}

// ---------------- merged edge pass: e -> exp(e), accumulate denominator ----------------
// softmax is shift-invariant; |e| is small here so exp() cannot overflow.
__global__ void edge_pass12(const int* __restrict__ src, const int* __restrict__ dst) {
    int i = blockIdx.x * blockDim.x + threadIdx.x;
    if (i >= ETOT) return;
    int s = (i < N_EDGES) ? src[i] : (i - N_EDGES);
    int d = (i < N_EDGES) ? dst[i] : (i - N_EDGES);
    float e = g_es[s] + g_ed[d];
    e = (e >= 0.f) ? e : 0.2f * e;   // leaky_relu 0.2
    float ex = __expf(e);
    g_ebuf[i] = ex;
    atomicAdd(&g_s[d], ex);
}

// one warp per edge: message = alpha*hg[src] + norm*hc[src], atomically added to hnew[dst]
__global__ void edge_pass3(const int* __restrict__ src, const int* __restrict__ dst, int outsel) {
    int e = (blockIdx.x * blockDim.x + threadIdx.x) >> 5;
    int lane = threadIdx.x & 31;
    if (e >= ETOT) return;
    float* hnew = outsel ? g_bufB : g_bufA;
    int s = (e < N_EDGES) ? src[e] : (e - N_EDGES);
    int d = (e < N_EDGES) ? dst[e] : (e - N_EDGES);
    float alpha = g_ebuf[e] / g_s[d];
    float gn = g_dinv[s] * g_dinv[d];
    float4 vg = *(const float4*)&g_hg[(size_t)s * D + lane * 4];
    float4 vc = *(const float4*)&g_hc[(size_t)s * D + lane * 4];
    float4 v;
    v.x = alpha * vg.x + gn * vc.x;
    v.y = alpha * vg.y + gn * vc.y;
    v.z = alpha * vg.z + gn * vc.z;
    v.w = alpha * vg.w + gn * vc.w;
    atomicAdd((float4*)&hnew[(size_t)d * D + lane * 4], v);
}

// ---------------- pooling ----------------
__global__ void pool_kernel(const int* __restrict__ batch) {
    int w = (blockIdx.x * blockDim.x + threadIdx.x) >> 5;
    int lane = threadIdx.x & 31;
    int n0 = w * 8;
    if (n0 >= N_NODES) return;
    float4 acc = make_float4(0.f, 0.f, 0.f, 0.f);
    int curg = batch[n0];
    for (int j = 0; j < 8; j++) {
        int n = n0 + j;
        if (n >= N_NODES) break;
        int g = batch[n];
        if (g != curg) {
            atomicAdd((float4*)&g_pooled[(size_t)curg * D + lane * 4], acc);
            acc = make_float4(0.f, 0.f, 0.f, 0.f);
            curg = g;
        }
        float4 v = *(const float4*)&g_bufA[(size_t)n * D + lane * 4];
        acc.x += v.x; acc.y += v.y; acc.z += v.z; acc.w += v.w;
    }
    atomicAdd((float4*)&g_pooled[(size_t)curg * D + lane * 4], acc);
}

__global__ void final_kernel(const float* __restrict__ lin4W, const float* __restrict__ lin4b,
                             float* __restrict__ out) {
    int t = threadIdx.x;
    if (t < NG * 2) {
        int g = t >> 1, o = t & 1;
        float inv = 1.0f / fmaxf(g_cnt[g], 1.0f);
        float sum = 0.f;
        for (int k = 0; k < D; k++) sum += g_pooled[g * D + k] * lin4W[k * 2 + o];
        out[t] = sum * inv + lin4b[o];
    }
}

// ---------------- launch ----------------
extern "C" void kernel_launch(void* const* d_in, const int* in_sizes, int n_in,
                              void* d_out, int out_size) {
    const float* x     = (const float*)d_in[0];
    const float* gatW  = (const float*)d_in[1];
    const float* gata  = (const float*)d_in[2];
    const float* gatb  = (const float*)d_in[3];
    const float* gcnW  = (const float*)d_in[4];
    const float* gcnb  = (const float*)d_in[5];
    const float* linW  = (const float*)d_in[6];
    const float* linb  = (const float*)d_in[7];
    const float* lin4W = (const float*)d_in[8];
    const float* lin4b = (const float*)d_in[9];
    const int*   src   = (const int*)d_in[10];
    const int*   dst   = (const int*)d_in[11];
    const int*   batch = (const int*)d_in[12];
    float* out = (float*)d_out;
    (void)in_sizes; (void)n_in; (void)out_size;

    cudaFuncSetAttribute(gemm4, cudaFuncAttributeMaxDynamicSharedMemorySize, SMEM_TOTAL_G);

    zero_kernel<<<(N_NODES + 255) / 256, 256>>>();
    deg_kernel<<<(ETOT + 255) / 256, 256>>>(dst);
    deg_fin_kernel<<<(N_NODES + 255) / 256, 256>>>(batch);

    for (int i = 0; i < 3; i++) {
        int insel  = (i == 0) ? 0 : ((i == 1) ? 1 : 2);   // x, bufA, bufB
        int outsel = (i == 1) ? 1 : 0;                    // bufA, bufB, bufA
        int relu   = (i > 0) ? 1 : 0;
        dim3 grid((N_NODES + 127) / 128, 3);
        gemm4<<<grid, 256, SMEM_TOTAL_G>>>(x, insel, relu,
                                           gatW + i * D * D, gcnW + i * D * D, linW + i * D * D,
                                           gatb + i * D, gcnb + i * D, linb + i * D,
                                           gata + i * 2 * D, gata + i * 2 * D + D, outsel);
        edge_pass12<<<(ETOT + 255) / 256, 256>>>(src, dst);
        edge_pass3<<<((size_t)ETOT * 32 + 255) / 256, 256>>>(src, dst, outsel);
    }

    pool_kernel<<<((N_NODES / 8) * 32 + 255) / 256, 256>>>(batch);
    final_kernel<<<1, 128>>>(lin4W, lin4b, out);
}

// round 7
// speedup vs baseline: 1.3146x; 1.3146x over previous
#include <cuda_runtime.h>
#include <math.h>

#define N_NODES 20000
#define N_EDGES 320000
#define D 128
#define ETOT (N_EDGES + N_NODES)   // edges + self-loops = 340000
#define NG 64

// ---------------- scratch (device globals; no allocation allowed) ----------------
__device__ float g_bufA[N_NODES * D];
__device__ float g_bufB[N_NODES * D];
__device__ float g_hg[N_NODES * D];     // h @ gat_W
__device__ float g_hc[N_NODES * D];     // h @ gcn_W
__device__ float g_es[N_NODES];         // h . (gat_W @ a_src)
__device__ float g_ed[N_NODES];         // h . (gat_W @ a_dst)
__device__ float g_s[N_NODES];          // segment sum of exp
__device__ float g_dinv[N_NODES];       // deg^-1/2 (also used as deg accumulator)
__device__ float g_ebuf[ETOT];          // per-edge exp(e)
__device__ float g_pooled[NG * D];
__device__ float g_cnt[NG];
__device__ float g_va[D];               // gat_W @ a_src
__device__ float g_vb[D];               // gat_W @ a_dst

// ---------------- helpers ----------------
__device__ __forceinline__ unsigned f2tf32(float a) {
    unsigned r;
    asm("cvt.rna.tf32.f32 %0, %1;" : "=r"(r) : "f"(a));
    return r;
}

__device__ __forceinline__ void mma_tf32(float* c, unsigned a0, unsigned a1, unsigned a2,
                                         unsigned a3, unsigned b0, unsigned b1) {
    asm volatile(
        "mma.sync.aligned.m16n8k8.row.col.f32.tf32.tf32.f32 "
        "{%0,%1,%2,%3}, {%4,%5,%6,%7}, {%8,%9}, {%0,%1,%2,%3};"
        : "+f"(c[0]), "+f"(c[1]), "+f"(c[2]), "+f"(c[3])
        : "r"(a0), "r"(a1), "r"(a2), "r"(a3), "r"(b0), "r"(b1));
}

// ---------------- setup kernels ----------------
__global__ void zero_kernel() {
    int i = blockIdx.x * blockDim.x + threadIdx.x;
    if (i < N_NODES) g_dinv[i] = 0.0f;
    if (i < NG * D)  g_pooled[i] = 0.0f;
    if (i < NG)      g_cnt[i] = 0.0f;
}

__global__ void deg_kernel(const int* __restrict__ dst) {
    int i = blockIdx.x * blockDim.x + threadIdx.x;
    if (i >= ETOT) return;
    int d = (i < N_EDGES) ? dst[i] : (i - N_EDGES);
    atomicAdd(&g_dinv[d], 1.0f);
}

__global__ void deg_fin_kernel(const int* __restrict__ batch) {
    int i = blockIdx.x * blockDim.x + threadIdx.x;
    if (i >= N_NODES) return;
    g_dinv[i] = rsqrtf(fmaxf(g_dinv[i], 1.0f));
    atomicAdd(&g_cnt[batch[i]], 1.0f);
}

// ---------------- va/vb: gat_W @ a_src, gat_W @ a_dst (tiny) ----------------
__global__ void wvec_kernel(const float* __restrict__ W, const float* __restrict__ a0,
                            const float* __restrict__ a1) {
    int t = threadIdx.x;
    int k = t & 127;
    const float* av = (t < 128) ? a0 : a1;
    float* outv = (t < 128) ? g_va : g_vb;
    float sum = 0.f;
    for (int n = 0; n < D; n++) sum += W[k * D + n] * av[n];
    outv[k] = sum;
}

// ---------------- node prep: es/ed from input h (+ optional relu), init g_s ----------------
// flags: bit0 = relu, bits[1:] = insel (0 = x, 1 = bufA, 2 = bufB)
__global__ void node_prep2(const float* __restrict__ x, int flags) {
    int node = (blockIdx.x * blockDim.x + threadIdx.x) >> 5;
    int lane = threadIdx.x & 31;
    if (node >= N_NODES) return;
    int relu = flags & 1;
    int insel = flags >> 1;
    const float* hin = (insel == 0) ? x : ((insel == 1) ? g_bufA : g_bufB);
    float4 v  = *(const float4*)&hin[(size_t)node * D + lane * 4];
    if (relu) {
        v.x = fmaxf(v.x, 0.f); v.y = fmaxf(v.y, 0.f);
        v.z = fmaxf(v.z, 0.f); v.w = fmaxf(v.w, 0.f);
    }
    float4 va = *(const float4*)&g_va[lane * 4];
    float4 vb = *(const float4*)&g_vb[lane * 4];
    float p0 = v.x * va.x + v.y * va.y + v.z * va.z + v.w * va.w;
    float p1 = v.x * vb.x + v.y * vb.y + v.z * vb.z + v.w * vb.w;
#pragma unroll
    for (int o = 16; o > 0; o >>= 1) {
        p0 += __shfl_xor_sync(0xFFFFFFFFu, p0, o);
        p1 += __shfl_xor_sync(0xFFFFFFFFu, p1, o);
    }
    if (lane == 0) {
        g_es[node] = p0;
        g_ed[node] = p1;
        g_s[node] = 0.0f;
    }
}

// ---------------- GEMM v5: 3xTF32 mma, lane-ordered fragment-major B, A from gmem ----------------
// Block: 128 rows x 64 cols, 8 warps (16 rows x 64 cols each), K=128.
// grid = (157, 2, 3): x = row block, y = column half, z = matrix (gat/gcn/lin).
// smem holds only the W-half split hi/lo in MMA-fragment order:
//   Bf4[(nt*16 + kt)*32 + lane], payload for CUDA lane id `lane` (gid=lane>>2, tig=lane&3):
//   (hi[k0+tig][n], lo[k0+tig][n], hi[k0+tig+4][n], lo[k0+tig+4][n]), n = n0+gid
// -> prologue STS.128 and mainloop LDS.128 are lane-consecutive => conflict-free.
#define NTB 8                               // n-tiles per block (64 cols)
#define BFRAG_BYTES (NTB * 16 * 32 * 16)    // 65536
#define SMEM_TOTAL_G (BFRAG_BYTES + 64 * 4)

__global__ void __launch_bounds__(256, 3)
gemm5(const float* __restrict__ x, int insel, int relu,
      const float* __restrict__ gatW, const float* __restrict__ gcnW,
      const float* __restrict__ linW,
      const float* __restrict__ gat_b, const float* __restrict__ gcn_b,
      const float* __restrict__ lin_b,
      int outsel) {
    extern __shared__ char smraw[];
    float4* Bf4   = (float4*)smraw;
    float*  biasS = (float*)(smraw + BFRAG_BYTES);   // 64

    const float* hin = (insel == 0) ? x : ((insel == 1) ? g_bufA : g_bufB);
    int mat = blockIdx.z;
    const float* W = (mat == 0) ? gatW : ((mat == 1) ? gcnW : linW);
    float* out = (mat == 0) ? g_hg : ((mat == 1) ? g_hc : (outsel ? g_bufB : g_bufA));

    int row0 = blockIdx.x * 128;
    int col0 = blockIdx.y * 64;
    int tid = threadIdx.x;
    int warp = tid >> 5;
    int lane = tid & 31;
    int gid = lane >> 2;   // groupID 0..7
    int tig = lane & 3;    // thread-in-group 0..3

    // ---- prologue: load W half, split tf32 hi/lo, store fragment-major ----
    for (int it = 0; it < 16; it++) {
        int f = warp * 16 + it;
        int nt = f >> 4, kt = f & 15;
        int k = kt * 8 + tig;
        int n = col0 + nt * 8 + gid;
        float w0 = W[k * D + n];
        float w1 = W[(k + 4) * D + n];
        unsigned h0 = f2tf32(w0);
        unsigned l0 = f2tf32(w0 - __uint_as_float(h0));
        unsigned h1 = f2tf32(w1);
        unsigned l1 = f2tf32(w1 - __uint_as_float(h1));
        Bf4[f * 32 + lane] = make_float4(__uint_as_float(h0), __uint_as_float(l0),
                                         __uint_as_float(h1), __uint_as_float(l1));
    }
    if (tid < 64) {
        int c = col0 + tid;
        biasS[tid] = (mat == 2) ? (lin_b[c] + gat_b[c] + gcn_b[c]) : 0.f;
    }
    __syncthreads();

    int mrow0 = warp * 16;
    int rA = row0 + mrow0 + gid;
    int rB = rA + 8;
    bool okA = rA < N_NODES, okB = rB < N_NODES;

    float acc[NTB][4];
#pragma unroll
    for (int nt = 0; nt < NTB; nt++)
#pragma unroll
        for (int j = 0; j < 4; j++) acc[nt][j] = 0.f;

#pragma unroll 2
    for (int kt = 0; kt < 16; kt++) {
        int k0 = kt * 8;
        float av[4];
        av[0] = okA ? hin[(size_t)rA * D + k0 + tig] : 0.f;
        av[1] = okB ? hin[(size_t)rB * D + k0 + tig] : 0.f;
        av[2] = okA ? hin[(size_t)rA * D + k0 + tig + 4] : 0.f;
        av[3] = okB ? hin[(size_t)rB * D + k0 + tig + 4] : 0.f;
        unsigned ah[4], al[4];
#pragma unroll
        for (int j = 0; j < 4; j++) {
            float a = relu ? fmaxf(av[j], 0.f) : av[j];
            ah[j] = f2tf32(a);
            al[j] = f2tf32(a - __uint_as_float(ah[j]));
        }
#pragma unroll
        for (int nt = 0; nt < NTB; nt++) {
            float4 b = Bf4[(nt * 16 + kt) * 32 + lane];   // conflict-free LDS.128
            unsigned bh0 = __float_as_uint(b.x), bl0 = __float_as_uint(b.y);
            unsigned bh1 = __float_as_uint(b.z), bl1 = __float_as_uint(b.w);
            mma_tf32(acc[nt], ah[0], ah[1], ah[2], ah[3], bh0, bh1);
            mma_tf32(acc[nt], ah[0], ah[1], ah[2], ah[3], bl0, bl1);
            mma_tf32(acc[nt], al[0], al[1], al[2], al[3], bh0, bh1);
        }
    }

    // ---- epilogue: bias + store.
    // C layout: c0,c1 -> (row gid, cols 2tig, 2tig+1); c2,c3 -> (row gid+8). ----
#pragma unroll
    for (int nt = 0; nt < NTB; nt++) {
        int lc = nt * 8 + tig * 2;
        int col = col0 + lc;
        float b0 = biasS[lc], b1 = biasS[lc + 1];
        if (okA)
            *(float2*)&out[(size_t)rA * D + col] = make_float2(acc[nt][0] + b0, acc[nt][1] + b1);
        if (okB)
            *(float2*)&out[(size_t)rB * D + col] = make_float2(acc[nt][2] + b0, acc[nt][3] + b1);
    }
}

// ---------------- merged edge pass: e -> exp(e), accumulate denominator ----------------
// softmax is shift-invariant; |e| is small here so exp() cannot overflow.
__global__ void edge_pass12(const int* __restrict__ src, const int* __restrict__ dst) {
    int i = blockIdx.x * blockDim.x + threadIdx.x;
    if (i >= ETOT) return;
    int s = (i < N_EDGES) ? src[i] : (i - N_EDGES);
    int d = (i < N_EDGES) ? dst[i] : (i - N_EDGES);
    float e = g_es[s] + g_ed[d];
    e = (e >= 0.f) ? e : 0.2f * e;   // leaky_relu 0.2
    float ex = __expf(e);
    g_ebuf[i] = ex;
    atomicAdd(&g_s[d], ex);
}

// one warp per edge: message = alpha*hg[src] + norm*hc[src], atomically added to hnew[dst]
__global__ void edge_pass3(const int* __restrict__ src, const int* __restrict__ dst, int outsel) {
    int e = (blockIdx.x * blockDim.x + threadIdx.x) >> 5;
    int lane = threadIdx.x & 31;
    if (e >= ETOT) return;
    float* hnew = outsel ? g_bufB : g_bufA;
    int s = (e < N_EDGES) ? src[e] : (e - N_EDGES);
    int d = (e < N_EDGES) ? dst[e] : (e - N_EDGES);
    float alpha = g_ebuf[e] / g_s[d];
    float gn = g_dinv[s] * g_dinv[d];
    float4 vg = *(const float4*)&g_hg[(size_t)s * D + lane * 4];
    float4 vc = *(const float4*)&g_hc[(size_t)s * D + lane * 4];
    float4 v;
    v.x = alpha * vg.x + gn * vc.x;
    v.y = alpha * vg.y + gn * vc.y;
    v.z = alpha * vg.z + gn * vc.z;
    v.w = alpha * vg.w + gn * vc.w;
    atomicAdd((float4*)&hnew[(size_t)d * D + lane * 4], v);
}

// ---------------- pooling ----------------
__global__ void pool_kernel(const int* __restrict__ batch) {
    int w = (blockIdx.x * blockDim.x + threadIdx.x) >> 5;
    int lane = threadIdx.x & 31;
    int n0 = w * 8;
    if (n0 >= N_NODES) return;
    float4 acc = make_float4(0.f, 0.f, 0.f, 0.f);
    int curg = batch[n0];
    for (int j = 0; j < 8; j++) {
        int n = n0 + j;
        if (n >= N_NODES) break;
        int g = batch[n];
        if (g != curg) {
            atomicAdd((float4*)&g_pooled[(size_t)curg * D + lane * 4], acc);
            acc = make_float4(0.f, 0.f, 0.f, 0.f);
            curg = g;
        }
        float4 v = *(const float4*)&g_bufA[(size_t)n * D + lane * 4];
        acc.x += v.x; acc.y += v.y; acc.z += v.z; acc.w += v.w;
    }
    atomicAdd((float4*)&g_pooled[(size_t)curg * D + lane * 4], acc);
}

__global__ void final_kernel(const float* __restrict__ lin4W, const float* __restrict__ lin4b,
                             float* __restrict__ out) {
    int t = threadIdx.x;
    if (t < NG * 2) {
        int g = t >> 1, o = t & 1;
        float inv = 1.0f / fmaxf(g_cnt[g], 1.0f);
        float sum = 0.f;
        for (int k = 0; k < D; k++) sum += g_pooled[g * D + k] * lin4W[k * 2 + o];
        out[t] = sum * inv + lin4b[o];
    }
}

// ---------------- launch ----------------
extern "C" void kernel_launch(void* const* d_in, const int* in_sizes, int n_in,
                              void* d_out, int out_size) {
    const float* x     = (const float*)d_in[0];
    const float* gatW  = (const float*)d_in[1];
    const float* gata  = (const float*)d_in[2];
    const float* gatb  = (const float*)d_in[3];
    const float* gcnW  = (const float*)d_in[4];
    const float* gcnb  = (const float*)d_in[5];
    const float* linW  = (const float*)d_in[6];
    const float* linb  = (const float*)d_in[7];
    const float* lin4W = (const float*)d_in[8];
    const float* lin4b = (const float*)d_in[9];
    const int*   src   = (const int*)d_in[10];
    const int*   dst   = (const int*)d_in[11];
    const int*   batch = (const int*)d_in[12];
    float* out = (float*)d_out;
    (void)in_sizes; (void)n_in; (void)out_size;

    cudaFuncSetAttribute(gemm5, cudaFuncAttributeMaxDynamicSharedMemorySize, SMEM_TOTAL_G);

    zero_kernel<<<(N_NODES + 255) / 256, 256>>>();
    deg_kernel<<<(ETOT + 255) / 256, 256>>>(dst);
    deg_fin_kernel<<<(N_NODES + 255) / 256, 256>>>(batch);

    for (int i = 0; i < 3; i++) {
        int insel  = (i == 0) ? 0 : ((i == 1) ? 1 : 2);   // x, bufA, bufB
        int outsel = (i == 1) ? 1 : 0;                    // bufA, bufB, bufA
        int relu   = (i > 0) ? 1 : 0;

        wvec_kernel<<<1, 256>>>(gatW + i * D * D, gata + i * 2 * D, gata + i * 2 * D + D);

        dim3 grid((N_NODES + 127) / 128, 2, 3);
        gemm5<<<grid, 256, SMEM_TOTAL_G>>>(x, insel, relu,
                                           gatW + i * D * D, gcnW + i * D * D, linW + i * D * D,
                                           gatb + i * D, gcnb + i * D, linb + i * D, outsel);

        node_prep2<<<(N_NODES * 32 + 255) / 256, 256>>>(x, relu | (insel << 1));

        edge_pass12<<<(ETOT + 255) / 256, 256>>>(src, dst);
        edge_pass3<<<((size_t)ETOT * 32 + 255) / 256, 256>>>(src, dst, outsel);
    }

    pool_kernel<<<((N_NODES / 8) * 32 + 255) / 256, 256>>>(batch);
    final_kernel<<<1, 128>>>(lin4W, lin4b, out);
}

// round 8
// speedup vs baseline: 1.5542x; 1.1823x over previous
#include <cuda_runtime.h>
#include <math.h>

#define N_NODES 20000
#define N_EDGES 320000
#define D 128
#define ETOT (N_EDGES + N_NODES)   // edges + self-loops = 340000
#define NG 64

// ---------------- scratch (device globals; no allocation allowed) ----------------
__device__ float g_bufA[N_NODES * D];
__device__ float g_bufB[N_NODES * D];
__device__ float g_hg[N_NODES * D];     // h @ gat_W
__device__ float g_hc[N_NODES * D];     // h @ gcn_W
__device__ float g_es[N_NODES];         // hg . a_src (atomic-accumulated)
__device__ float g_ed[N_NODES];         // hg . a_dst (atomic-accumulated)
__device__ float g_s[N_NODES];          // segment sum of exp
__device__ float g_dinv[N_NODES];       // deg^-1/2 (also used as deg accumulator)
__device__ float g_ebuf[ETOT];          // per-edge exp(e)
__device__ float g_pooled[NG * D];
__device__ float g_cnt[NG];

// ---------------- helpers ----------------
__device__ __forceinline__ unsigned f2tf32(float a) {
    unsigned r;
    asm("cvt.rna.tf32.f32 %0, %1;" : "=r"(r) : "f"(a));
    return r;
}

__device__ __forceinline__ void mma_tf32(float* c, unsigned a0, unsigned a1, unsigned a2,
                                         unsigned a3, unsigned b0, unsigned b1) {
    asm volatile(
        "mma.sync.aligned.m16n8k8.row.col.f32.tf32.tf32.f32 "
        "{%0,%1,%2,%3}, {%4,%5,%6,%7}, {%8,%9}, {%0,%1,%2,%3};"
        : "+f"(c[0]), "+f"(c[1]), "+f"(c[2]), "+f"(c[3])
        : "r"(a0), "r"(a1), "r"(a2), "r"(a3), "r"(b0), "r"(b1));
}

// ---------------- setup kernels ----------------
__global__ void zero_kernel() {
    int i = blockIdx.x * blockDim.x + threadIdx.x;
    if (i < N_NODES) g_dinv[i] = 0.0f;
    if (i < NG * D)  g_pooled[i] = 0.0f;
    if (i < NG)      g_cnt[i] = 0.0f;
}

__global__ void deg_kernel(const int* __restrict__ dst) {
    int i = blockIdx.x * blockDim.x + threadIdx.x;
    if (i >= ETOT) return;
    int d = (i < N_EDGES) ? dst[i] : (i - N_EDGES);
    atomicAdd(&g_dinv[d], 1.0f);
}

__global__ void deg_fin_kernel(const int* __restrict__ batch) {
    int i = blockIdx.x * blockDim.x + threadIdx.x;
    if (i >= N_NODES) return;
    g_dinv[i] = rsqrtf(fmaxf(g_dinv[i], 1.0f));
    atomicAdd(&g_cnt[batch[i]], 1.0f);
}

// per-layer: zero es/ed/s so gemm5's epilogue can atomically accumulate
__global__ void zero_esed_kernel() {
    int i = blockIdx.x * blockDim.x + threadIdx.x;
    if (i < N_NODES) { g_es[i] = 0.f; g_ed[i] = 0.f; g_s[i] = 0.f; }
}

// ---------------- GEMM v6: 3xTF32 mma, lane-ordered fragment-major B, A from gmem ----------------
// Block: 128 rows x 64 cols, 8 warps (16 rows x 64 cols each), K=128.
// grid = (157, 2, 3): x = row block, y = column half, z = matrix (gat/gcn/lin).
// mat==0 epilogue accumulates partial es/ed (over this block's 64 cols) via atomicAdd.
// smem holds only the W-half split hi/lo in MMA-fragment order:
//   Bf4[(nt*16 + kt)*32 + lane], payload for CUDA lane id `lane` (gid=lane>>2, tig=lane&3):
//   (hi[k0+tig][n], lo[k0+tig][n], hi[k0+tig+4][n], lo[k0+tig+4][n]), n = n0+gid
// -> prologue STS.128 and mainloop LDS.128 are lane-consecutive => conflict-free.
#define NTB 8                               // n-tiles per block (64 cols)
#define BFRAG_BYTES (NTB * 16 * 32 * 16)    // 65536
#define SMEM_TOTAL_G (BFRAG_BYTES + 3 * 64 * 4)

__global__ void __launch_bounds__(256, 3)
gemm6(const float* __restrict__ x, int insel, int relu,
      const float* __restrict__ gatW, const float* __restrict__ gcnW,
      const float* __restrict__ linW,
      const float* __restrict__ gat_b, const float* __restrict__ gcn_b,
      const float* __restrict__ lin_b,
      const float* __restrict__ a0v, const float* __restrict__ a1v,
      int outsel) {
    extern __shared__ char smraw[];
    float4* Bf4   = (float4*)smraw;
    float*  biasS = (float*)(smraw + BFRAG_BYTES);   // 64
    float*  a0S   = biasS + 64;                      // 64 (this col-half of a_src)
    float*  a1S   = a0S + 64;                        // 64 (this col-half of a_dst)

    const float* hin = (insel == 0) ? x : ((insel == 1) ? g_bufA : g_bufB);
    int mat = blockIdx.z;
    const float* W = (mat == 0) ? gatW : ((mat == 1) ? gcnW : linW);
    float* out = (mat == 0) ? g_hg : ((mat == 1) ? g_hc : (outsel ? g_bufB : g_bufA));

    int row0 = blockIdx.x * 128;
    int col0 = blockIdx.y * 64;
    int tid = threadIdx.x;
    int warp = tid >> 5;
    int lane = tid & 31;
    int gid = lane >> 2;   // groupID 0..7
    int tig = lane & 3;    // thread-in-group 0..3

    // ---- prologue: load W half, split tf32 hi/lo, store fragment-major ----
    for (int it = 0; it < 16; it++) {
        int f = warp * 16 + it;
        int nt = f >> 4, kt = f & 15;
        int k = kt * 8 + tig;
        int n = col0 + nt * 8 + gid;
        float w0 = W[k * D + n];
        float w1 = W[(k + 4) * D + n];
        unsigned h0 = f2tf32(w0);
        unsigned l0 = f2tf32(w0 - __uint_as_float(h0));
        unsigned h1 = f2tf32(w1);
        unsigned l1 = f2tf32(w1 - __uint_as_float(h1));
        Bf4[f * 32 + lane] = make_float4(__uint_as_float(h0), __uint_as_float(l0),
                                         __uint_as_float(h1), __uint_as_float(l1));
    }
    if (tid < 64) {
        int c = col0 + tid;
        biasS[tid] = (mat == 2) ? (lin_b[c] + gat_b[c] + gcn_b[c]) : 0.f;
        if (mat == 0) { a0S[tid] = a0v[c]; a1S[tid] = a1v[c]; }
    }
    __syncthreads();

    int mrow0 = warp * 16;
    int rA = row0 + mrow0 + gid;
    int rB = rA + 8;
    bool okA = rA < N_NODES, okB = rB < N_NODES;

    float acc[NTB][4];
#pragma unroll
    for (int nt = 0; nt < NTB; nt++)
#pragma unroll
        for (int j = 0; j < 4; j++) acc[nt][j] = 0.f;

#pragma unroll 2
    for (int kt = 0; kt < 16; kt++) {
        int k0 = kt * 8;
        float av[4];
        av[0] = okA ? hin[(size_t)rA * D + k0 + tig] : 0.f;
        av[1] = okB ? hin[(size_t)rB * D + k0 + tig] : 0.f;
        av[2] = okA ? hin[(size_t)rA * D + k0 + tig + 4] : 0.f;
        av[3] = okB ? hin[(size_t)rB * D + k0 + tig + 4] : 0.f;
        unsigned ah[4], al[4];
#pragma unroll
        for (int j = 0; j < 4; j++) {
            float a = relu ? fmaxf(av[j], 0.f) : av[j];
            ah[j] = f2tf32(a);
            al[j] = f2tf32(a - __uint_as_float(ah[j]));
        }
#pragma unroll
        for (int nt = 0; nt < NTB; nt++) {
            float4 b = Bf4[(nt * 16 + kt) * 32 + lane];   // conflict-free LDS.128
            unsigned bh0 = __float_as_uint(b.x), bl0 = __float_as_uint(b.y);
            unsigned bh1 = __float_as_uint(b.z), bl1 = __float_as_uint(b.w);
            mma_tf32(acc[nt], ah[0], ah[1], ah[2], ah[3], bh0, bh1);
            mma_tf32(acc[nt], ah[0], ah[1], ah[2], ah[3], bl0, bl1);
            mma_tf32(acc[nt], al[0], al[1], al[2], al[3], bh0, bh1);
        }
    }

    // ---- epilogue: bias + store.
    // C layout: c0,c1 -> (row gid, cols 2tig, 2tig+1); c2,c3 -> (row gid+8). ----
#pragma unroll
    for (int nt = 0; nt < NTB; nt++) {
        int lc = nt * 8 + tig * 2;
        int col = col0 + lc;
        float b0 = biasS[lc], b1 = biasS[lc + 1];
        if (okA)
            *(float2*)&out[(size_t)rA * D + col] = make_float2(acc[nt][0] + b0, acc[nt][1] + b1);
        if (okB)
            *(float2*)&out[(size_t)rB * D + col] = make_float2(acc[nt][2] + b0, acc[nt][3] + b1);
    }

    // ---- fused partial es/ed for GAT matrix (this block's 64-col contribution) ----
    if (mat == 0) {
        float esA = 0.f, edA = 0.f, esB = 0.f, edB = 0.f;
#pragma unroll
        for (int nt = 0; nt < NTB; nt++) {
            int lc = nt * 8 + tig * 2;
            float p0 = a0S[lc], p1 = a0S[lc + 1];
            float q0 = a1S[lc], q1 = a1S[lc + 1];
            esA += acc[nt][0] * p0 + acc[nt][1] * p1;
            edA += acc[nt][0] * q0 + acc[nt][1] * q1;
            esB += acc[nt][2] * p0 + acc[nt][3] * p1;
            edB += acc[nt][2] * q0 + acc[nt][3] * q1;
        }
        // reduce across the 4 tig lanes (xor 1, 2 stays within the 4-lane group)
#pragma unroll
        for (int o = 1; o < 4; o <<= 1) {
            esA += __shfl_xor_sync(0xFFFFFFFFu, esA, o);
            edA += __shfl_xor_sync(0xFFFFFFFFu, edA, o);
            esB += __shfl_xor_sync(0xFFFFFFFFu, esB, o);
            edB += __shfl_xor_sync(0xFFFFFFFFu, edB, o);
        }
        if (tig == 0) {
            if (okA) { atomicAdd(&g_es[rA], esA); atomicAdd(&g_ed[rA], edA); }
            if (okB) { atomicAdd(&g_es[rB], esB); atomicAdd(&g_ed[rB], edB); }
        }
    }
}

// ---------------- merged edge pass: e -> exp(e), accumulate denominator ----------------
// softmax is shift-invariant; |e| is small here so exp() cannot overflow.
__global__ void edge_pass12(const int* __restrict__ src, const int* __restrict__ dst) {
    int i = blockIdx.x * blockDim.x + threadIdx.x;
    if (i >= ETOT) return;
    int s = (i < N_EDGES) ? src[i] : (i - N_EDGES);
    int d = (i < N_EDGES) ? dst[i] : (i - N_EDGES);
    float e = g_es[s] + g_ed[d];
    e = (e >= 0.f) ? e : 0.2f * e;   // leaky_relu 0.2
    float ex = __expf(e);
    g_ebuf[i] = ex;
    atomicAdd(&g_s[d], ex);
}

// one warp per edge: message = alpha*hg[src] + norm*hc[src], atomically added to hnew[dst]
__global__ void edge_pass3(const int* __restrict__ src, const int* __restrict__ dst, int outsel) {
    int e = (blockIdx.x * blockDim.x + threadIdx.x) >> 5;
    int lane = threadIdx.x & 31;
    if (e >= ETOT) return;
    float* hnew = outsel ? g_bufB : g_bufA;
    int s = (e < N_EDGES) ? src[e] : (e - N_EDGES);
    int d = (e < N_EDGES) ? dst[e] : (e - N_EDGES);
    float alpha = g_ebuf[e] / g_s[d];
    float gn = g_dinv[s] * g_dinv[d];
    float4 vg = *(const float4*)&g_hg[(size_t)s * D + lane * 4];
    float4 vc = *(const float4*)&g_hc[(size_t)s * D + lane * 4];
    float4 v;
    v.x = alpha * vg.x + gn * vc.x;
    v.y = alpha * vg.y + gn * vc.y;
    v.z = alpha * vg.z + gn * vc.z;
    v.w = alpha * vg.w + gn * vc.w;
    atomicAdd((float4*)&hnew[(size_t)d * D + lane * 4], v);
}

// ---------------- pooling ----------------
__global__ void pool_kernel(const int* __restrict__ batch) {
    int w = (blockIdx.x * blockDim.x + threadIdx.x) >> 5;
    int lane = threadIdx.x & 31;
    int n0 = w * 8;
    if (n0 >= N_NODES) return;
    float4 acc = make_float4(0.f, 0.f, 0.f, 0.f);
    int curg = batch[n0];
    for (int j = 0; j < 8; j++) {
        int n = n0 + j;
        if (n >= N_NODES) break;
        int g = batch[n];
        if (g != curg) {
            atomicAdd((float4*)&g_pooled[(size_t)curg * D + lane * 4], acc);
            acc = make_float4(0.f, 0.f, 0.f, 0.f);
            curg = g;
        }
        float4 v = *(const float4*)&g_bufA[(size_t)n * D + lane * 4];
        acc.x += v.x; acc.y += v.y; acc.z += v.z; acc.w += v.w;
    }
    atomicAdd((float4*)&g_pooled[(size_t)curg * D + lane * 4], acc);
}

__global__ void final_kernel(const float* __restrict__ lin4W, const float* __restrict__ lin4b,
                             float* __restrict__ out) {
    int t = threadIdx.x;
    if (t < NG * 2) {
        int g = t >> 1, o = t & 1;
        float inv = 1.0f / fmaxf(g_cnt[g], 1.0f);
        float sum = 0.f;
        for (int k = 0; k < D; k++) sum += g_pooled[g * D + k] * lin4W[k * 2 + o];
        out[t] = sum * inv + lin4b[o];
    }
}

// ---------------- launch ----------------
extern "C" void kernel_launch(void* const* d_in, const int* in_sizes, int n_in,
                              void* d_out, int out_size) {
    const float* x     = (const float*)d_in[0];
    const float* gatW  = (const float*)d_in[1];
    const float* gata  = (const float*)d_in[2];
    const float* gatb  = (const float*)d_in[3];
    const float* gcnW  = (const float*)d_in[4];
    const float* gcnb  = (const float*)d_in[5];
    const float* linW  = (const float*)d_in[6];
    const float* linb  = (const float*)d_in[7];
    const float* lin4W = (const float*)d_in[8];
    const float* lin4b = (const float*)d_in[9];
    const int*   src   = (const int*)d_in[10];
    const int*   dst   = (const int*)d_in[11];
    const int*   batch = (const int*)d_in[12];
    float* out = (float*)d_out;
    (void)in_sizes; (void)n_in; (void)out_size;

    cudaFuncSetAttribute(gemm6, cudaFuncAttributeMaxDynamicSharedMemorySize, SMEM_TOTAL_G);

    zero_kernel<<<(N_NODES + 255) / 256, 256>>>();
    deg_kernel<<<(ETOT + 255) / 256, 256>>>(dst);
    deg_fin_kernel<<<(N_NODES + 255) / 256, 256>>>(batch);

    for (int i = 0; i < 3; i++) {
        int insel  = (i == 0) ? 0 : ((i == 1) ? 1 : 2);   // x, bufA, bufB
        int outsel = (i == 1) ? 1 : 0;                    // bufA, bufB, bufA
        int relu   = (i > 0) ? 1 : 0;

        zero_esed_kernel<<<(N_NODES + 255) / 256, 256>>>();

        dim3 grid((N_NODES + 127) / 128, 2, 3);
        gemm6<<<grid, 256, SMEM_TOTAL_G>>>(x, insel, relu,
                                           gatW + i * D * D, gcnW + i * D * D, linW + i * D * D,
                                           gatb + i * D, gcnb + i * D, linb + i * D,
                                           gata + i * 2 * D, gata + i * 2 * D + D, outsel);

        edge_pass12<<<(ETOT + 255) / 256, 256>>>(src, dst);
        edge_pass3<<<((size_t)ETOT * 32 + 255) / 256, 256>>>(src, dst, outsel);
    }

    pool_kernel<<<((N_NODES / 8) * 32 + 255) / 256, 256>>>(batch);
    final_kernel<<<1, 128>>>(lin4W, lin4b, out);
}

// round 9
// speedup vs baseline: 1.6951x; 1.0906x over previous
#include <cuda_runtime.h>
#include <math.h>

#define N_NODES 20000
#define N_EDGES 320000
#define D 128
#define ETOT (N_EDGES + N_NODES)   // edges + self-loops = 340000
#define NG 64

// ---------------- scratch (device globals; no allocation allowed) ----------------
__device__ float g_bufA[N_NODES * D];
__device__ float g_bufB[N_NODES * D];
__device__ float g_hg[N_NODES * D];     // h @ gat_W
__device__ float g_hc[N_NODES * D];     // h @ gcn_W
__device__ float g_es[N_NODES];         // hg . a_src (atomic-accumulated)
__device__ float g_ed[N_NODES];         // hg . a_dst (atomic-accumulated)
__device__ float g_dinv[N_NODES];       // deg^-1/2
__device__ float g_pooled[NG * D];
__device__ float g_cnt[NG];
// CSR (built once; degrees are layer-invariant)
__device__ int g_degi[N_NODES];         // int in-degree counts
__device__ int g_rowptr[N_NODES + 1];
__device__ int g_cursor[N_NODES];
__device__ int g_esrc[ETOT];            // src node per CSR slot (grouped by dst)

// ---------------- helpers ----------------
__device__ __forceinline__ unsigned f2tf32(float a) {
    unsigned r;
    asm("cvt.rna.tf32.f32 %0, %1;" : "=r"(r) : "f"(a));
    return r;
}

__device__ __forceinline__ void mma_tf32(float* c, unsigned a0, unsigned a1, unsigned a2,
                                         unsigned a3, unsigned b0, unsigned b1) {
    asm volatile(
        "mma.sync.aligned.m16n8k8.row.col.f32.tf32.tf32.f32 "
        "{%0,%1,%2,%3}, {%4,%5,%6,%7}, {%8,%9}, {%0,%1,%2,%3};"
        : "+f"(c[0]), "+f"(c[1]), "+f"(c[2]), "+f"(c[3])
        : "r"(a0), "r"(a1), "r"(a2), "r"(a3), "r"(b0), "r"(b1));
}

// ---------------- setup kernels ----------------
__global__ void zero_kernel() {
    int i = blockIdx.x * blockDim.x + threadIdx.x;
    if (i < N_NODES) g_degi[i] = 0;
    if (i < NG * D)  g_pooled[i] = 0.0f;
    if (i < NG)      g_cnt[i] = 0.0f;
}

__global__ void deg_kernel(const int* __restrict__ dst) {
    int i = blockIdx.x * blockDim.x + threadIdx.x;
    if (i >= ETOT) return;
    int d = (i < N_EDGES) ? dst[i] : (i - N_EDGES);
    atomicAdd(&g_degi[d], 1);
}

__global__ void deg_fin_kernel(const int* __restrict__ batch) {
    int i = blockIdx.x * blockDim.x + threadIdx.x;
    if (i >= N_NODES) return;
    g_dinv[i] = rsqrtf(fmaxf((float)g_degi[i], 1.0f));
    atomicAdd(&g_cnt[batch[i]], 1.0f);
}

// single-block exclusive scan of g_degi -> g_rowptr (and cursor init)
__global__ void scan_kernel() {
    __shared__ int buf[1024];
    __shared__ int carry;
    int t = threadIdx.x;
    if (t == 0) carry = 0;
    __syncthreads();
    for (int base = 0; base < N_NODES; base += 1024) {
        int i = base + t;
        int v = (i < N_NODES) ? g_degi[i] : 0;
        buf[t] = v;
        __syncthreads();
        // Hillis-Steele inclusive scan
        for (int o = 1; o < 1024; o <<= 1) {
            int add = (t >= o) ? buf[t - o] : 0;
            __syncthreads();
            buf[t] += add;
            __syncthreads();
        }
        int incl = buf[t];
        if (i < N_NODES) {
            g_rowptr[i] = carry + incl - v;   // exclusive
            g_cursor[i] = carry + incl - v;
        }
        __syncthreads();
        if (t == 1023) carry += buf[1023];
        __syncthreads();
    }
    if (t == 0) g_rowptr[N_NODES] = carry;
}

__global__ void scatter_kernel(const int* __restrict__ src, const int* __restrict__ dst) {
    int i = blockIdx.x * blockDim.x + threadIdx.x;
    if (i >= ETOT) return;
    int s = (i < N_EDGES) ? src[i] : (i - N_EDGES);
    int d = (i < N_EDGES) ? dst[i] : (i - N_EDGES);
    int pos = atomicAdd(&g_cursor[d], 1);
    g_esrc[pos] = s;
}

// per-layer: zero es/ed so gemm6's epilogue can atomically accumulate
__global__ void zero_esed_kernel() {
    int i = blockIdx.x * blockDim.x + threadIdx.x;
    if (i < N_NODES) { g_es[i] = 0.f; g_ed[i] = 0.f; }
}

// ---------------- GEMM v6: 3xTF32 mma, lane-ordered fragment-major B, A from gmem ----------------
// Block: 128 rows x 64 cols, 8 warps (16 rows x 64 cols each), K=128.
// grid = (157, 2, 3): x = row block, y = column half, z = matrix (gat/gcn/lin).
// mat==0 epilogue accumulates partial es/ed (over this block's 64 cols) via atomicAdd.
#define NTB 8                               // n-tiles per block (64 cols)
#define BFRAG_BYTES (NTB * 16 * 32 * 16)    // 65536
#define SMEM_TOTAL_G (BFRAG_BYTES + 3 * 64 * 4)

__global__ void __launch_bounds__(256, 3)
gemm6(const float* __restrict__ x, int insel, int relu,
      const float* __restrict__ gatW, const float* __restrict__ gcnW,
      const float* __restrict__ linW,
      const float* __restrict__ gat_b, const float* __restrict__ gcn_b,
      const float* __restrict__ lin_b,
      const float* __restrict__ a0v, const float* __restrict__ a1v,
      int outsel) {
    extern __shared__ char smraw[];
    float4* Bf4   = (float4*)smraw;
    float*  biasS = (float*)(smraw + BFRAG_BYTES);   // 64
    float*  a0S   = biasS + 64;                      // 64
    float*  a1S   = a0S + 64;                        // 64

    const float* hin = (insel == 0) ? x : ((insel == 1) ? g_bufA : g_bufB);
    int mat = blockIdx.z;
    const float* W = (mat == 0) ? gatW : ((mat == 1) ? gcnW : linW);
    float* out = (mat == 0) ? g_hg : ((mat == 1) ? g_hc : (outsel ? g_bufB : g_bufA));

    int row0 = blockIdx.x * 128;
    int col0 = blockIdx.y * 64;
    int tid = threadIdx.x;
    int warp = tid >> 5;
    int lane = tid & 31;
    int gid = lane >> 2;
    int tig = lane & 3;

    for (int it = 0; it < 16; it++) {
        int f = warp * 16 + it;
        int nt = f >> 4, kt = f & 15;
        int k = kt * 8 + tig;
        int n = col0 + nt * 8 + gid;
        float w0 = W[k * D + n];
        float w1 = W[(k + 4) * D + n];
        unsigned h0 = f2tf32(w0);
        unsigned l0 = f2tf32(w0 - __uint_as_float(h0));
        unsigned h1 = f2tf32(w1);
        unsigned l1 = f2tf32(w1 - __uint_as_float(h1));
        Bf4[f * 32 + lane] = make_float4(__uint_as_float(h0), __uint_as_float(l0),
                                         __uint_as_float(h1), __uint_as_float(l1));
    }
    if (tid < 64) {
        int c = col0 + tid;
        biasS[tid] = (mat == 2) ? (lin_b[c] + gat_b[c] + gcn_b[c]) : 0.f;
        if (mat == 0) { a0S[tid] = a0v[c]; a1S[tid] = a1v[c]; }
    }
    __syncthreads();

    int mrow0 = warp * 16;
    int rA = row0 + mrow0 + gid;
    int rB = rA + 8;
    bool okA = rA < N_NODES, okB = rB < N_NODES;

    float acc[NTB][4];
#pragma unroll
    for (int nt = 0; nt < NTB; nt++)
#pragma unroll
        for (int j = 0; j < 4; j++) acc[nt][j] = 0.f;

#pragma unroll 2
    for (int kt = 0; kt < 16; kt++) {
        int k0 = kt * 8;
        float av[4];
        av[0] = okA ? hin[(size_t)rA * D + k0 + tig] : 0.f;
        av[1] = okB ? hin[(size_t)rB * D + k0 + tig] : 0.f;
        av[2] = okA ? hin[(size_t)rA * D + k0 + tig + 4] : 0.f;
        av[3] = okB ? hin[(size_t)rB * D + k0 + tig + 4] : 0.f;
        unsigned ah[4], al[4];
#pragma unroll
        for (int j = 0; j < 4; j++) {
            float a = relu ? fmaxf(av[j], 0.f) : av[j];
            ah[j] = f2tf32(a);
            al[j] = f2tf32(a - __uint_as_float(ah[j]));
        }
#pragma unroll
        for (int nt = 0; nt < NTB; nt++) {
            float4 b = Bf4[(nt * 16 + kt) * 32 + lane];
            unsigned bh0 = __float_as_uint(b.x), bl0 = __float_as_uint(b.y);
            unsigned bh1 = __float_as_uint(b.z), bl1 = __float_as_uint(b.w);
            mma_tf32(acc[nt], ah[0], ah[1], ah[2], ah[3], bh0, bh1);
            mma_tf32(acc[nt], ah[0], ah[1], ah[2], ah[3], bl0, bl1);
            mma_tf32(acc[nt], al[0], al[1], al[2], al[3], bh0, bh1);
        }
    }

#pragma unroll
    for (int nt = 0; nt < NTB; nt++) {
        int lc = nt * 8 + tig * 2;
        int col = col0 + lc;
        float b0 = biasS[lc], b1 = biasS[lc + 1];
        if (okA)
            *(float2*)&out[(size_t)rA * D + col] = make_float2(acc[nt][0] + b0, acc[nt][1] + b1);
        if (okB)
            *(float2*)&out[(size_t)rB * D + col] = make_float2(acc[nt][2] + b0, acc[nt][3] + b1);
    }

    if (mat == 0) {
        float esA = 0.f, edA = 0.f, esB = 0.f, edB = 0.f;
#pragma unroll
        for (int nt = 0; nt < NTB; nt++) {
            int lc = nt * 8 + tig * 2;
            float p0 = a0S[lc], p1 = a0S[lc + 1];
            float q0 = a1S[lc], q1 = a1S[lc + 1];
            esA += acc[nt][0] * p0 + acc[nt][1] * p1;
            edA += acc[nt][0] * q0 + acc[nt][1] * q1;
            esB += acc[nt][2] * p0 + acc[nt][3] * p1;
            edB += acc[nt][2] * q0 + acc[nt][3] * q1;
        }
#pragma unroll
        for (int o = 1; o < 4; o <<= 1) {
            esA += __shfl_xor_sync(0xFFFFFFFFu, esA, o);
            edA += __shfl_xor_sync(0xFFFFFFFFu, edA, o);
            esB += __shfl_xor_sync(0xFFFFFFFFu, esB, o);
            edB += __shfl_xor_sync(0xFFFFFFFFu, edB, o);
        }
        if (tig == 0) {
            if (okA) { atomicAdd(&g_es[rA], esA); atomicAdd(&g_ed[rA], edA); }
            if (okB) { atomicAdd(&g_es[rB], esB); atomicAdd(&g_ed[rB], edB); }
        }
    }
}

// ---------------- fused CSR edge gather: softmax denom + message accumulate ----------------
// One warp per destination node. No atomics, no per-edge buffers.
// hnew[d] already holds lin(h)+biases from gemm6; we add the GAT+GCN messages and store.
__global__ void __launch_bounds__(256, 8)
edge_gather(int outsel) {
    int d = (blockIdx.x * blockDim.x + threadIdx.x) >> 5;
    int lane = threadIdx.x & 31;
    if (d >= N_NODES) return;
    float* hnew = outsel ? g_bufB : g_bufA;

    int beg = g_rowptr[d];
    int end = g_rowptr[d + 1];
    float edd = g_ed[d];
    float dinvd = g_dinv[d];

    // pass 1: softmax denominator (lane-parallel over edges)
    float sum = 0.f;
    for (int j = beg + lane; j < end; j += 32) {
        int s = g_esrc[j];
        float e = g_es[s] + edd;
        e = (e >= 0.f) ? e : 0.2f * e;
        sum += __expf(e);
    }
#pragma unroll
    for (int o = 16; o > 0; o >>= 1) sum += __shfl_xor_sync(0xFFFFFFFFu, sum, o);
    float inv_denom = 1.0f / sum;   // deg >= 1 (self-loop) so sum > 0

    // pass 2: accumulate messages (warp-cooperative per edge, lanes split D)
    float4 acc = *(const float4*)&hnew[(size_t)d * D + lane * 4];
    for (int j = beg; j < end; j++) {
        int s = g_esrc[j];                       // uniform across warp -> broadcast
        float e = g_es[s] + edd;
        e = (e >= 0.f) ? e : 0.2f * e;
        float alpha = __expf(e) * inv_denom;
        float gn = g_dinv[s] * dinvd;
        float4 vg = *(const float4*)&g_hg[(size_t)s * D + lane * 4];
        float4 vc = *(const float4*)&g_hc[(size_t)s * D + lane * 4];
        acc.x += alpha * vg.x + gn * vc.x;
        acc.y += alpha * vg.y + gn * vc.y;
        acc.z += alpha * vg.z + gn * vc.z;
        acc.w += alpha * vg.w + gn * vc.w;
    }
    *(float4*)&hnew[(size_t)d * D + lane * 4] = acc;
}

// ---------------- pooling ----------------
__global__ void pool_kernel(const int* __restrict__ batch) {
    int w = (blockIdx.x * blockDim.x + threadIdx.x) >> 5;
    int lane = threadIdx.x & 31;
    int n0 = w * 8;
    if (n0 >= N_NODES) return;
    float4 acc = make_float4(0.f, 0.f, 0.f, 0.f);
    int curg = batch[n0];
    for (int j = 0; j < 8; j++) {
        int n = n0 + j;
        if (n >= N_NODES) break;
        int g = batch[n];
        if (g != curg) {
            atomicAdd((float4*)&g_pooled[(size_t)curg * D + lane * 4], acc);
            acc = make_float4(0.f, 0.f, 0.f, 0.f);
            curg = g;
        }
        float4 v = *(const float4*)&g_bufA[(size_t)n * D + lane * 4];
        acc.x += v.x; acc.y += v.y; acc.z += v.z; acc.w += v.w;
    }
    atomicAdd((float4*)&g_pooled[(size_t)curg * D + lane * 4], acc);
}

__global__ void final_kernel(const float* __restrict__ lin4W, const float* __restrict__ lin4b,
                             float* __restrict__ out) {
    int t = threadIdx.x;
    if (t < NG * 2) {
        int g = t >> 1, o = t & 1;
        float inv = 1.0f / fmaxf(g_cnt[g], 1.0f);
        float sum = 0.f;
        for (int k = 0; k < D; k++) sum += g_pooled[g * D + k] * lin4W[k * 2 + o];
        out[t] = sum * inv + lin4b[o];
    }
}

// ---------------- launch ----------------
extern "C" void kernel_launch(void* const* d_in, const int* in_sizes, int n_in,
                              void* d_out, int out_size) {
    const float* x     = (const float*)d_in[0];
    const float* gatW  = (const float*)d_in[1];
    const float* gata  = (const float*)d_in[2];
    const float* gatb  = (const float*)d_in[3];
    const float* gcnW  = (const float*)d_in[4];
    const float* gcnb  = (const float*)d_in[5];
    const float* linW  = (const float*)d_in[6];
    const float* linb  = (const float*)d_in[7];
    const float* lin4W = (const float*)d_in[8];
    const float* lin4b = (const float*)d_in[9];
    const int*   src   = (const int*)d_in[10];
    const int*   dst   = (const int*)d_in[11];
    const int*   batch = (const int*)d_in[12];
    float* out = (float*)d_out;
    (void)in_sizes; (void)n_in; (void)out_size;

    cudaFuncSetAttribute(gemm6, cudaFuncAttributeMaxDynamicSharedMemorySize, SMEM_TOTAL_G);

    // one-time CSR build + degree norms
    zero_kernel<<<(N_NODES + 255) / 256, 256>>>();
    deg_kernel<<<(ETOT + 255) / 256, 256>>>(dst);
    deg_fin_kernel<<<(N_NODES + 255) / 256, 256>>>(batch);
    scan_kernel<<<1, 1024>>>();
    scatter_kernel<<<(ETOT + 255) / 256, 256>>>(src, dst);

    for (int i = 0; i < 3; i++) {
        int insel  = (i == 0) ? 0 : ((i == 1) ? 1 : 2);   // x, bufA, bufB
        int outsel = (i == 1) ? 1 : 0;                    // bufA, bufB, bufA
        int relu   = (i > 0) ? 1 : 0;

        zero_esed_kernel<<<(N_NODES + 255) / 256, 256>>>();

        dim3 grid((N_NODES + 127) / 128, 2, 3);
        gemm6<<<grid, 256, SMEM_TOTAL_G>>>(x, insel, relu,
                                           gatW + i * D * D, gcnW + i * D * D, linW + i * D * D,
                                           gatb + i * D, gcnb + i * D, linb + i * D,
                                           gata + i * 2 * D, gata + i * 2 * D + D, outsel);

        edge_gather<<<(N_NODES * 32 + 255) / 256, 256>>>(outsel);
    }

    pool_kernel<<<((N_NODES / 8) * 32 + 255) / 256, 256>>>(batch);
    final_kernel<<<1, 128>>>(lin4W, lin4b, out);
}

// round 11
// speedup vs baseline: 1.7511x; 1.0330x over previous
#include <cuda_runtime.h>
#include <math.h>

#define N_NODES 20000
#define N_EDGES 320000
#define D 128
#define ETOT (N_EDGES + N_NODES)   // edges + self-loops = 340000
#define NG 64

// ---------------- scratch (device globals; no allocation allowed) ----------------
__device__ float g_bufA[N_NODES * D];
__device__ float g_bufB[N_NODES * D];
__device__ float g_hg[N_NODES * D];     // h @ gat_W
__device__ float g_hc[N_NODES * D];     // h @ gcn_W
__device__ float g_esp[2 * N_NODES];    // partial hg.a_src per column-half (plain stores)
__device__ float g_edp[2 * N_NODES];    // partial hg.a_dst per column-half
__device__ float g_dinv[N_NODES];       // deg^-1/2
__device__ float g_pooled[NG * D];
__device__ float g_cnt[NG];
// CSR (built once; degrees are layer-invariant)
__device__ int g_degi[N_NODES];         // int in-degree counts
__device__ int g_rowptr[N_NODES + 1];
__device__ int g_cursor[N_NODES];
__device__ int g_esrc[ETOT];            // src node per CSR slot (grouped by dst)

// ---------------- helpers ----------------
__device__ __forceinline__ unsigned f2tf32(float a) {
    unsigned r;
    asm("cvt.rna.tf32.f32 %0, %1;" : "=r"(r) : "f"(a));
    return r;
}

__device__ __forceinline__ void mma_tf32(float* c, unsigned a0, unsigned a1, unsigned a2,
                                         unsigned a3, unsigned b0, unsigned b1) {
    asm volatile(
        "mma.sync.aligned.m16n8k8.row.col.f32.tf32.tf32.f32 "
        "{%0,%1,%2,%3}, {%4,%5,%6,%7}, {%8,%9}, {%0,%1,%2,%3};"
        : "+f"(c[0]), "+f"(c[1]), "+f"(c[2]), "+f"(c[3])
        : "r"(a0), "r"(a1), "r"(a2), "r"(a3), "r"(b0), "r"(b1));
}

// ---------------- setup kernels ----------------
__global__ void zero_kernel() {
    int i = blockIdx.x * blockDim.x + threadIdx.x;
    if (i < N_NODES) g_degi[i] = 0;
    if (i < NG * D)  g_pooled[i] = 0.0f;
    if (i < NG)      g_cnt[i] = 0.0f;
}

__global__ void deg_kernel(const int* __restrict__ dst) {
    int i = blockIdx.x * blockDim.x + threadIdx.x;
    if (i >= ETOT) return;
    int d = (i < N_EDGES) ? dst[i] : (i - N_EDGES);
    atomicAdd(&g_degi[d], 1);
}

__global__ void deg_fin_kernel(const int* __restrict__ batch) {
    int i = blockIdx.x * blockDim.x + threadIdx.x;
    if (i >= N_NODES) return;
    g_dinv[i] = rsqrtf(fmaxf((float)g_degi[i], 1.0f));
    atomicAdd(&g_cnt[batch[i]], 1.0f);
}

// single-block exclusive scan of g_degi -> g_rowptr, shfl-hierarchical (fast)
__global__ void scan_kernel() {
    __shared__ int wsum[32];
    __shared__ int s_carry;
    int t = threadIdx.x;
    int lane = t & 31, wid = t >> 5;
    if (t == 0) s_carry = 0;
    __syncthreads();
    for (int base = 0; base < N_NODES; base += 1024) {
        int i = base + t;
        int v = (i < N_NODES) ? g_degi[i] : 0;
        // warp inclusive scan
        int incl = v;
#pragma unroll
        for (int o = 1; o < 32; o <<= 1) {
            int n = __shfl_up_sync(0xFFFFFFFFu, incl, o);
            if (lane >= o) incl += n;
        }
        if (lane == 31) wsum[wid] = incl;
        __syncthreads();
        if (wid == 0) {
            int w = wsum[lane];
            int wincl = w;
#pragma unroll
            for (int o = 1; o < 32; o <<= 1) {
                int n = __shfl_up_sync(0xFFFFFFFFu, wincl, o);
                if (lane >= o) wincl += n;
            }
            wsum[lane] = wincl - w;   // exclusive warp offsets
        }
        __syncthreads();
        int carry = s_carry;
        int excl = carry + wsum[wid] + incl - v;
        if (i < N_NODES) {
            g_rowptr[i] = excl;
            g_cursor[i] = excl;
        }
        __syncthreads();
        if (t == 1023) s_carry = carry + wsum[31] + incl;
        __syncthreads();
    }
    if (t == 0) g_rowptr[N_NODES] = s_carry;
}

__global__ void scatter_kernel(const int* __restrict__ src, const int* __restrict__ dst) {
    int i = blockIdx.x * blockDim.x + threadIdx.x;
    if (i >= ETOT) return;
    int s = (i < N_EDGES) ? src[i] : (i - N_EDGES);
    int d = (i < N_EDGES) ? dst[i] : (i - N_EDGES);
    int pos = atomicAdd(&g_cursor[d], 1);
    g_esrc[pos] = s;
}

// ---------------- GEMM v6: 3xTF32 mma, lane-ordered fragment-major B, A from gmem ----------------
// Block: 128 rows x 64 cols, 8 warps (16 rows x 64 cols each), K=128.
// grid = (157, 2, 3): x = row block, y = column half, z = matrix (gat/gcn/lin).
// mat==0 epilogue plain-stores its partial es/ed into g_esp/g_edp[half*N + row].
#define NTB 8                               // n-tiles per block (64 cols)
#define BFRAG_BYTES (NTB * 16 * 32 * 16)    // 65536
#define SMEM_TOTAL_G (BFRAG_BYTES + 3 * 64 * 4)

__global__ void __launch_bounds__(256, 3)
gemm6(const float* __restrict__ x, int insel, int relu,
      const float* __restrict__ gatW, const float* __restrict__ gcnW,
      const float* __restrict__ linW,
      const float* __restrict__ gat_b, const float* __restrict__ gcn_b,
      const float* __restrict__ lin_b,
      const float* __restrict__ a0v, const float* __restrict__ a1v,
      int outsel) {
    extern __shared__ char smraw[];
    float4* Bf4   = (float4*)smraw;
    float*  biasS = (float*)(smraw + BFRAG_BYTES);   // 64
    float*  a0S   = biasS + 64;                      // 64
    float*  a1S   = a0S + 64;                        // 64

    const float* hin = (insel == 0) ? x : ((insel == 1) ? g_bufA : g_bufB);
    int mat = blockIdx.z;
    const float* W = (mat == 0) ? gatW : ((mat == 1) ? gcnW : linW);
    float* out = (mat == 0) ? g_hg : ((mat == 1) ? g_hc : (outsel ? g_bufB : g_bufA));

    int row0 = blockIdx.x * 128;
    int half = blockIdx.y;
    int col0 = half * 64;
    int tid = threadIdx.x;
    int warp = tid >> 5;
    int lane = tid & 31;
    int gid = lane >> 2;
    int tig = lane & 3;

    for (int it = 0; it < 16; it++) {
        int f = warp * 16 + it;
        int nt = f >> 4, kt = f & 15;
        int k = kt * 8 + tig;
        int n = col0 + nt * 8 + gid;
        float w0 = W[k * D + n];
        float w1 = W[(k + 4) * D + n];
        unsigned h0 = f2tf32(w0);
        unsigned l0 = f2tf32(w0 - __uint_as_float(h0));
        unsigned h1 = f2tf32(w1);
        unsigned l1 = f2tf32(w1 - __uint_as_float(h1));
        Bf4[f * 32 + lane] = make_float4(__uint_as_float(h0), __uint_as_float(l0),
                                         __uint_as_float(h1), __uint_as_float(l1));
    }
    if (tid < 64) {
        int c = col0 + tid;
        biasS[tid] = (mat == 2) ? (lin_b[c] + gat_b[c] + gcn_b[c]) : 0.f;
        if (mat == 0) { a0S[tid] = a0v[c]; a1S[tid] = a1v[c]; }
    }
    __syncthreads();

    int mrow0 = warp * 16;
    int rA = row0 + mrow0 + gid;
    int rB = rA + 8;
    bool okA = rA < N_NODES, okB = rB < N_NODES;

    float acc[NTB][4];
#pragma unroll
    for (int nt = 0; nt < NTB; nt++)
#pragma unroll
        for (int j = 0; j < 4; j++) acc[nt][j] = 0.f;

#pragma unroll 2
    for (int kt = 0; kt < 16; kt++) {
        int k0 = kt * 8;
        float av[4];
        av[0] = okA ? hin[(size_t)rA * D + k0 + tig] : 0.f;
        av[1] = okB ? hin[(size_t)rB * D + k0 + tig] : 0.f;
        av[2] = okA ? hin[(size_t)rA * D + k0 + tig + 4] : 0.f;
        av[3] = okB ? hin[(size_t)rB * D + k0 + tig + 4] : 0.f;
        unsigned ah[4], al[4];
#pragma unroll
        for (int j = 0; j < 4; j++) {
            float a = relu ? fmaxf(av[j], 0.f) : av[j];
            ah[j] = f2tf32(a);
            al[j] = f2tf32(a - __uint_as_float(ah[j]));
        }
#pragma unroll
        for (int nt = 0; nt < NTB; nt++) {
            float4 b = Bf4[(nt * 16 + kt) * 32 + lane];
            unsigned bh0 = __float_as_uint(b.x), bl0 = __float_as_uint(b.y);
            unsigned bh1 = __float_as_uint(b.z), bl1 = __float_as_uint(b.w);
            mma_tf32(acc[nt], ah[0], ah[1], ah[2], ah[3], bh0, bh1);
            mma_tf32(acc[nt], ah[0], ah[1], ah[2], ah[3], bl0, bl1);
            mma_tf32(acc[nt], al[0], al[1], al[2], al[3], bh0, bh1);
        }
    }

#pragma unroll
    for (int nt = 0; nt < NTB; nt++) {
        int lc = nt * 8 + tig * 2;
        int col = col0 + lc;
        float b0 = biasS[lc], b1 = biasS[lc + 1];
        if (okA)
            *(float2*)&out[(size_t)rA * D + col] = make_float2(acc[nt][0] + b0, acc[nt][1] + b1);
        if (okB)
            *(float2*)&out[(size_t)rB * D + col] = make_float2(acc[nt][2] + b0, acc[nt][3] + b1);
    }

    if (mat == 0) {
        float esA = 0.f, edA = 0.f, esB = 0.f, edB = 0.f;
#pragma unroll
        for (int nt = 0; nt < NTB; nt++) {
            int lc = nt * 8 + tig * 2;
            float p0 = a0S[lc], p1 = a0S[lc + 1];
            float q0 = a1S[lc], q1 = a1S[lc + 1];
            esA += acc[nt][0] * p0 + acc[nt][1] * p1;
            edA += acc[nt][0] * q0 + acc[nt][1] * q1;
            esB += acc[nt][2] * p0 + acc[nt][3] * p1;
            edB += acc[nt][2] * q0 + acc[nt][3] * q1;
        }
#pragma unroll
        for (int o = 1; o < 4; o <<= 1) {
            esA += __shfl_xor_sync(0xFFFFFFFFu, esA, o);
            edA += __shfl_xor_sync(0xFFFFFFFFu, edA, o);
            esB += __shfl_xor_sync(0xFFFFFFFFu, esB, o);
            edB += __shfl_xor_sync(0xFFFFFFFFu, edB, o);
        }
        if (tig == 0) {
            int ofs = half * N_NODES;
            if (okA) { g_esp[ofs + rA] = esA; g_edp[ofs + rA] = edA; }
            if (okB) { g_esp[ofs + rB] = esB; g_edp[ofs + rB] = edB; }
        }
    }
}

// ---------------- fused CSR edge gather: softmax denom + message accumulate ----------------
// One warp per destination node. No atomics, no per-edge buffers.
// hnew[d] already holds lin(h)+biases from gemm6; we add the GAT+GCN messages and store.
__global__ void __launch_bounds__(256, 8)
edge_gather(int outsel) {
    int d = (blockIdx.x * blockDim.x + threadIdx.x) >> 5;
    int lane = threadIdx.x & 31;
    if (d >= N_NODES) return;
    float* hnew = outsel ? g_bufB : g_bufA;

    int beg = g_rowptr[d];
    int end = g_rowptr[d + 1];
    float edd = g_edp[d] + g_edp[N_NODES + d];
    float dinvd = g_dinv[d];

    // pass 1: softmax denominator (lane-parallel over edges)
    float sum = 0.f;
    for (int j = beg + lane; j < end; j += 32) {
        int s = g_esrc[j];
        float e = g_esp[s] + g_esp[N_NODES + s] + edd;
        e = (e >= 0.f) ? e : 0.2f * e;
        sum += __expf(e);
    }
#pragma unroll
    for (int o = 16; o > 0; o >>= 1) sum += __shfl_xor_sync(0xFFFFFFFFu, sum, o);
    float inv_denom = 1.0f / sum;   // deg >= 1 (self-loop) so sum > 0

    // pass 2: accumulate messages (warp-cooperative per edge, lanes split D)
    float4 acc = *(const float4*)&hnew[(size_t)d * D + lane * 4];
    for (int j = beg; j < end; j++) {
        int s = g_esrc[j];                       // uniform across warp -> broadcast
        float e = g_esp[s] + g_esp[N_NODES + s] + edd;
        e = (e >= 0.f) ? e : 0.2f * e;
        float alpha = __expf(e) * inv_denom;
        float gn = g_dinv[s] * dinvd;
        float4 vg = *(const float4*)&g_hg[(size_t)s * D + lane * 4];
        float4 vc = *(const float4*)&g_hc[(size_t)s * D + lane * 4];
        acc.x += alpha * vg.x + gn * vc.x;
        acc.y += alpha * vg.y + gn * vc.y;
        acc.z += alpha * vg.z + gn * vc.z;
        acc.w += alpha * vg.w + gn * vc.w;
    }
    *(float4*)&hnew[(size_t)d * D + lane * 4] = acc;
}

// ---------------- pooling ----------------
__global__ void pool_kernel(const int* __restrict__ batch) {
    int w = (blockIdx.x * blockDim.x + threadIdx.x) >> 5;
    int lane = threadIdx.x & 31;
    int n0 = w * 8;
    if (n0 >= N_NODES) return;
    float4 acc = make_float4(0.f, 0.f, 0.f, 0.f);
    int curg = batch[n0];
    for (int j = 0; j < 8; j++) {
        int n = n0 + j;
        if (n >= N_NODES) break;
        int g = batch[n];
        if (g != curg) {
            atomicAdd((float4*)&g_pooled[(size_t)curg * D + lane * 4], acc);
            acc = make_float4(0.f, 0.f, 0.f, 0.f);
            curg = g;
        }
        float4 v = *(const float4*)&g_bufA[(size_t)n * D + lane * 4];
        acc.x += v.x; acc.y += v.y; acc.z += v.z; acc.w += v.w;
    }
    atomicAdd((float4*)&g_pooled[(size_t)curg * D + lane * 4], acc);
}

__global__ void final_kernel(const float* __restrict__ lin4W, const float* __restrict__ lin4b,
                             float* __restrict__ out) {
    int t = threadIdx.x;
    if (t < NG * 2) {
        int g = t >> 1, o = t & 1;
        float inv = 1.0f / fmaxf(g_cnt[g], 1.0f);
        float sum = 0.f;
        for (int k = 0; k < D; k++) sum += g_pooled[g * D + k] * lin4W[k * 2 + o];
        out[t] = sum * inv + lin4b[o];
    }
}

// ---------------- launch ----------------
extern "C" void kernel_launch(void* const* d_in, const int* in_sizes, int n_in,
                              void* d_out, int out_size) {
    const float* x     = (const float*)d_in[0];
    const float* gatW  = (const float*)d_in[1];
    const float* gata  = (const float*)d_in[2];
    const float* gatb  = (const float*)d_in[3];
    const float* gcnW  = (const float*)d_in[4];
    const float* gcnb  = (const float*)d_in[5];
    const float* linW  = (const float*)d_in[6];
    const float* linb  = (const float*)d_in[7];
    const float* lin4W = (const float*)d_in[8];
    const float* lin4b = (const float*)d_in[9];
    const int*   src   = (const int*)d_in[10];
    const int*   dst   = (const int*)d_in[11];
    const int*   batch = (const int*)d_in[12];
    float* out = (float*)d_out;
    (void)in_sizes; (void)n_in; (void)out_size;

    cudaFuncSetAttribute(gemm6, cudaFuncAttributeMaxDynamicSharedMemorySize, SMEM_TOTAL_G);

    // one-time CSR build + degree norms
    zero_kernel<<<(N_NODES + 255) / 256, 256>>>();
    deg_kernel<<<(ETOT + 255) / 256, 256>>>(dst);
    deg_fin_kernel<<<(N_NODES + 255) / 256, 256>>>(batch);
    scan_kernel<<<1, 1024>>>();
    scatter_kernel<<<(ETOT + 255) / 256, 256>>>(src, dst);

    for (int i = 0; i < 3; i++) {
        int insel  = (i == 0) ? 0 : ((i == 1) ? 1 : 2);   // x, bufA, bufB
        int outsel = (i == 1) ? 1 : 0;                    // bufA, bufB, bufA
        int relu   = (i > 0) ? 1 : 0;

        dim3 grid((N_NODES + 127) / 128, 2, 3);
        gemm6<<<grid, 256, SMEM_TOTAL_G>>>(x, insel, relu,
                                           gatW + i * D * D, gcnW + i * D * D, linW + i * D * D,
                                           gatb + i * D, gcnb + i * D, linb + i * D,
                                           gata + i * 2 * D, gata + i * 2 * D + D, outsel);

        edge_gather<<<(N_NODES * 32 + 255) / 256, 256>>>(outsel);
    }

    pool_kernel<<<((N_NODES / 8) * 32 + 255) / 256, 256>>>(batch);
    final_kernel<<<1, 128>>>(lin4W, lin4b, out);
}